// round 7
// baseline (speedup 1.0000x reference)
#include <cuda_runtime.h>
#include <cuda_bf16.h>
#include <math.h>

// Problem constants (fixed by reference): values [256, 262144] fp32.
#define B 256
#define N 262144
#define VEC4_PER_ROW (N / 4)          // 65536 int4 per row
#define BLOCKS_PER_ROW 8
#define THREADS 512
#define VEC4_PER_BLOCK (VEC4_PER_ROW / BLOCKS_PER_ROW)    // 8192 int4 = 128KB contiguous
#define VEC4_PER_THREAD (VEC4_PER_BLOCK / THREADS)        // 16
#define TOTAL_BLOCKS (B * BLOCKS_PER_ROW)                 // 2048

// Deterministic scratch: every partial slot written every launch; ticket
// self-resets in the epilogue -> graph-replay safe, no init kernel.
__device__ unsigned int g_partials[B * BLOCKS_PER_ROW];
__device__ unsigned int g_ticket;

__device__ __forceinline__ int prmt_signbytes(int a, int b) {
    int r;
    // nibble 0xB = sign-replicate byte3 of a, 0xF = sign-replicate byte7 (b's byte3)
    asm("prmt.b32 %0, %1, %2, 0xFBFB;" : "=r"(r) : "r"(a), "r"(b));
    return r;
}

__device__ __forceinline__ int dp4a_acc(int a, int b, int c) {
    int r;
    asm("dp4a.s32.s32 %0, %1, %2, %3;" : "=r"(r) : "r"(a), "r"(b), "r"(c));
    return r;
}

__global__ void __launch_bounds__(THREADS) fused_entropy_kernel(
    const float* __restrict__ vals, float* __restrict__ out) {
    const int row = blockIdx.y;
    const int blk = blockIdx.x;

    // Contiguous 128KB region per block, streamed sequentially.
    // Plain loads (default cache policy) — testing whether .cs evict-first
    // was degrading L2 sector-fill behavior for the streaming read.
    const int4* __restrict__ p =
        reinterpret_cast<const int4*>(vals)
        + (size_t)row * VEC4_PER_ROW + (size_t)blk * VEC4_PER_BLOCK;

    // cnt accumulates -(#sign-bit-set) == -(#(x<0) incl. -0.0)
    int cnt = 0;
#pragma unroll
    for (int k = 0; k < VEC4_PER_THREAD; ++k) {
        int4 v = p[k * THREADS + threadIdx.x];   // default-policy LDG.128
        int s01 = prmt_signbytes(v.x, v.y);      // bytes0,1 = 0xFF if negative
        int s23 = prmt_signbytes(v.z, v.w);
        cnt = dp4a_acc(s01, 0x0101, cnt);        // -= negatives of x,y
        cnt = dp4a_acc(s23, 0x0101, cnt);        // -= negatives of z,w
    }
    cnt = -cnt;  // #negatives handled by this thread

    // warp reduce
#pragma unroll
    for (int o = 16; o > 0; o >>= 1)
        cnt += __shfl_xor_sync(0xFFFFFFFFu, cnt, o);

    // block reduce via smem (16 warps)
    __shared__ int warp_sums[THREADS / 32];
    __shared__ bool s_is_last;
    if ((threadIdx.x & 31) == 0)
        warp_sums[threadIdx.x >> 5] = cnt;
    __syncthreads();

    if (threadIdx.x == 0) {
        int s = 0;
#pragma unroll
        for (int w = 0; w < THREADS / 32; ++w) s += warp_sums[w];
        g_partials[row * BLOCKS_PER_ROW + blk] = (unsigned)s;
        __threadfence();  // publish partial before taking a ticket
        unsigned t = atomicAdd(&g_ticket, 1u);
        s_is_last = (t == TOTAL_BLOCKS - 1);
    }
    __syncthreads();

    if (!s_is_last) return;

    // ---- Last block: epilogue. One thread per batch row (first 256 threads). ----
    if (threadIdx.x < B) {
        const int r = threadIdx.x;
        unsigned c0 = 0;            // negatives == count0 (x <= 0; exact ±0.0 measure-zero)
#pragma unroll
        for (int i = 0; i < BLOCKS_PER_ROW; ++i)
            c0 += g_partials[r * BLOCKS_PER_ROW + i];

        const float n = (float)N;
        const float cc0 = (float)c0;
        const float cc1 = n - cc0;
        const float denom = n + 1e-8f;
        const float p0 = cc0 / denom;
        const float p1 = cc1 / denom;
        float t0 = (p0 > 0.0f) ? p0 * log2f(p0 + 1e-10f) : 0.0f;
        float t1 = (p1 > 0.0f) ? p1 * log2f(p1 + 1e-10f) : 0.0f;
        out[r] = -(t0 + t1);

        if (r == 0) g_ticket = 0u;  // reset for next graph replay (deterministic)
    }
}

extern "C" void kernel_launch(void* const* d_in, const int* in_sizes, int n_in,
                              void* d_out, int out_size) {
    const float* vals = (const float*)d_in[0];
    float* out = (float*)d_out;

    dim3 grid(BLOCKS_PER_ROW, B);
    fused_entropy_kernel<<<grid, THREADS>>>(vals, out);
}

// round 8
// speedup vs baseline: 1.0007x; 1.0007x over previous
#include <cuda_runtime.h>
#include <cuda_bf16.h>
#include <math.h>

// Problem constants (fixed by reference): values [256, 262144] fp32.
#define B 256
#define N 262144
#define V8_PER_ROW (N / 8)            // 32768 x 32B units per row
#define BLOCKS_PER_ROW 16
#define THREADS 256
#define THREADS_PER_ROW (BLOCKS_PER_ROW * THREADS)       // 4096
#define V8_PER_THREAD (V8_PER_ROW / THREADS_PER_ROW)     // 8 x 256-bit loads/thread
#define TOTAL_BLOCKS (B * BLOCKS_PER_ROW)                // 4096

// Deterministic scratch: every partial slot written every launch; ticket
// self-resets in the epilogue -> graph-replay safe, no init kernel.
__device__ unsigned int g_partials[B * BLOCKS_PER_ROW];
__device__ unsigned int g_ticket;

__device__ __forceinline__ int prmt_signbytes(int a, int b) {
    int r;
    // nibble 0xB = sign-replicate byte3 of a, 0xF = sign-replicate byte7 (b's byte3)
    asm("prmt.b32 %0, %1, %2, 0xFBFB;" : "=r"(r) : "r"(a), "r"(b));
    return r;
}

__device__ __forceinline__ int dp4a_acc(int a, int b, int c) {
    int r;
    asm("dp4a.s32.s32 %0, %1, %2, %3;" : "=r"(r) : "r"(a), "r"(b), "r"(c));
    return r;
}

// Blackwell (sm_100+) 256-bit global load: one warp request = 1024B = 8 lines.
__device__ __forceinline__ void ldg_v8(const float* __restrict__ a, int r[8]) {
    asm volatile("ld.global.v8.b32 {%0,%1,%2,%3,%4,%5,%6,%7}, [%8];"
                 : "=r"(r[0]), "=r"(r[1]), "=r"(r[2]), "=r"(r[3]),
                   "=r"(r[4]), "=r"(r[5]), "=r"(r[6]), "=r"(r[7])
                 : "l"(a));
}

__global__ void __launch_bounds__(THREADS) fused_entropy_kernel(
    const float* __restrict__ vals, float* __restrict__ out) {
    const int row = blockIdx.y;
    const int blk = blockIdx.x;

    const float* __restrict__ p =
        vals + (size_t)row * N + ((size_t)blk * THREADS + threadIdx.x) * 8;

    // cnt accumulates -(#sign-bit-set) == -(#(x<0) incl. -0.0)
    int cnt = 0;
#pragma unroll
    for (int k = 0; k < V8_PER_THREAD; ++k) {
        int v[8];
        ldg_v8(p + (size_t)k * THREADS_PER_ROW * 8, v);
#pragma unroll
        for (int j = 0; j < 4; ++j) {
            int s = prmt_signbytes(v[2 * j], v[2 * j + 1]);  // bytes0,1 = 0xFF if neg
            cnt = dp4a_acc(s, 0x0101, cnt);                  // -= negatives of the pair
        }
    }
    cnt = -cnt;  // #negatives handled by this thread

    // warp reduce
#pragma unroll
    for (int o = 16; o > 0; o >>= 1)
        cnt += __shfl_xor_sync(0xFFFFFFFFu, cnt, o);

    // block reduce via smem (8 warps)
    __shared__ int warp_sums[THREADS / 32];
    __shared__ bool s_is_last;
    if ((threadIdx.x & 31) == 0)
        warp_sums[threadIdx.x >> 5] = cnt;
    __syncthreads();

    if (threadIdx.x == 0) {
        int s = 0;
#pragma unroll
        for (int w = 0; w < THREADS / 32; ++w) s += warp_sums[w];
        g_partials[row * BLOCKS_PER_ROW + blk] = (unsigned)s;
        __threadfence();  // publish partial before taking a ticket
        unsigned t = atomicAdd(&g_ticket, 1u);
        s_is_last = (t == TOTAL_BLOCKS - 1);
    }
    __syncthreads();

    if (!s_is_last) return;

    // ---- Last block: epilogue. One thread per batch row. ----
    {
        const int r = threadIdx.x;  // THREADS == B == 256
        unsigned c0 = 0;            // negatives == count0 (x <= 0; exact ±0.0 measure-zero)
#pragma unroll
        for (int i = 0; i < BLOCKS_PER_ROW; ++i)
            c0 += g_partials[r * BLOCKS_PER_ROW + i];

        const float n = (float)N;
        const float cc0 = (float)c0;
        const float cc1 = n - cc0;
        const float denom = n + 1e-8f;
        const float p0 = cc0 / denom;
        const float p1 = cc1 / denom;
        float t0 = (p0 > 0.0f) ? p0 * log2f(p0 + 1e-10f) : 0.0f;
        float t1 = (p1 > 0.0f) ? p1 * log2f(p1 + 1e-10f) : 0.0f;
        out[r] = -(t0 + t1);

        if (r == 0) g_ticket = 0u;  // reset for next graph replay (deterministic)
    }
}

extern "C" void kernel_launch(void* const* d_in, const int* in_sizes, int n_in,
                              void* d_out, int out_size) {
    const float* vals = (const float*)d_in[0];
    float* out = (float*)d_out;

    dim3 grid(BLOCKS_PER_ROW, B);
    fused_entropy_kernel<<<grid, THREADS>>>(vals, out);
}

// round 9
// speedup vs baseline: 1.0523x; 1.0515x over previous
#include <cuda_runtime.h>
#include <cuda_bf16.h>
#include <math.h>

// Problem constants (fixed by reference): values [256, 262144] fp32.
#define B 256
#define N 262144
#define VEC4_PER_ROW (N / 4)          // 65536 int4 per row
#define BLOCKS_PER_ROW 16
#define THREADS 256
#define THREADS_PER_ROW (BLOCKS_PER_ROW * THREADS)        // 4096
#define VEC4_PER_THREAD (VEC4_PER_ROW / THREADS_PER_ROW)  // 16

// Per-row packed accumulator: low 32 bits = count0 sum, high 32 bits = #arrivals.
// The block taking the last arrival computes the row's entropy and resets the
// word to 0 -> deterministic and graph-replay safe, no init kernel, no fence.
__device__ unsigned long long g_row_acc[B];

__device__ __forceinline__ int prmt_signbytes(int a, int b) {
    int r;
    // nibble 0xB = sign-replicate byte3 of a, 0xF = sign-replicate byte7 (b's byte3)
    asm("prmt.b32 %0, %1, %2, 0xFBFB;" : "=r"(r) : "r"(a), "r"(b));
    return r;
}

__device__ __forceinline__ int dp4a_acc(int a, int b, int c) {
    int r;
    asm("dp4a.s32.s32 %0, %1, %2, %3;" : "=r"(r) : "r"(a), "r"(b), "r"(c));
    return r;
}

__global__ void __launch_bounds__(THREADS) fused_entropy_kernel(
    const float* __restrict__ vals, float* __restrict__ out) {
    const int row = blockIdx.y;
    const int blk = blockIdx.x;
    const int4* __restrict__ p =
        reinterpret_cast<const int4*>(vals) + (size_t)row * VEC4_PER_ROW;

    const int base = blk * THREADS + threadIdx.x;

    // cnt accumulates -(#sign-bit-set) == -(#(x<0) incl. -0.0) == -count0
    int cnt = 0;
#pragma unroll
    for (int k = 0; k < VEC4_PER_THREAD; ++k) {
        int4 v = __ldcs(&p[base + k * THREADS_PER_ROW]);  // read-once stream
        int s01 = prmt_signbytes(v.x, v.y);  // bytes0,1 = 0xFF if negative
        int s23 = prmt_signbytes(v.z, v.w);
        cnt = dp4a_acc(s01, 0x0101, cnt);    // -= negatives of x,y
        cnt = dp4a_acc(s23, 0x0101, cnt);    // -= negatives of z,w
    }
    cnt = -cnt;  // #negatives (count0) handled by this thread

    // warp reduce
#pragma unroll
    for (int o = 16; o > 0; o >>= 1)
        cnt += __shfl_xor_sync(0xFFFFFFFFu, cnt, o);

    // block reduce via smem (8 warps)
    __shared__ int warp_sums[THREADS / 32];
    if ((threadIdx.x & 31) == 0)
        warp_sums[threadIdx.x >> 5] = cnt;
    __syncthreads();

    if (threadIdx.x == 0) {
        int s = 0;
#pragma unroll
        for (int w = 0; w < THREADS / 32; ++w) s += warp_sums[w];

        // Single atomic: publish count AND take a ticket in one op.
        unsigned long long pkt = (1ULL << 32) | (unsigned long long)(unsigned)s;
        unsigned long long old = atomicAdd(&g_row_acc[row], pkt);
        unsigned arrivals_before = (unsigned)(old >> 32);

        if (arrivals_before == BLOCKS_PER_ROW - 1) {
            // This block completes the row: total count0 in-hand, no fence needed
            // (the value travelled through the atomic itself).
            unsigned c0 = (unsigned)old + (unsigned)s;

            const float n = (float)N;
            const float cc0 = (float)c0;
            const float cc1 = n - cc0;
            const float denom = n + 1e-8f;
            const float p0 = cc0 / denom;
            const float p1 = cc1 / denom;
            float t0 = (p0 > 0.0f) ? p0 * log2f(p0 + 1e-10f) : 0.0f;
            float t1 = (p1 > 0.0f) ? p1 * log2f(p1 + 1e-10f) : 0.0f;
            out[row] = -(t0 + t1);

            g_row_acc[row] = 0ULL;  // reset for next graph replay (deterministic)
        }
    }
}

extern "C" void kernel_launch(void* const* d_in, const int* in_sizes, int n_in,
                              void* d_out, int out_size) {
    const float* vals = (const float*)d_in[0];
    float* out = (float*)d_out;

    dim3 grid(BLOCKS_PER_ROW, B);
    fused_entropy_kernel<<<grid, THREADS>>>(vals, out);
}